// round 5
// baseline (speedup 1.0000x reference)
#include <cuda_runtime.h>

typedef unsigned long long ull;

// Chain state: 4-channel fields only. h1 ping-pong, h2 stored per block.
__device__ float g_h1[2][16][4][64][64];   //  2.1 MB
__device__ float g_h2[32][16][4][64][64];  // 33.6 MB

// ---- packed fp32x2 helpers --------------------------------------------------
__device__ __forceinline__ ull ffma2(ull a, ull b, ull c) {
    ull d; asm("fma.rn.f32x2 %0, %1, %2, %3;" : "=l"(d) : "l"(a), "l"(b), "l"(c)); return d;
}
__device__ __forceinline__ ull fadd2(ull a, ull b) {
    ull d; asm("add.rn.f32x2 %0, %1, %2;" : "=l"(d) : "l"(a), "l"(b)); return d;
}
__device__ __forceinline__ ull pack2(float lo, float hi) {
    ull d; asm("mov.b64 %0, {%1, %2};" : "=l"(d) : "f"(lo), "f"(hi)); return d;
}
__device__ __forceinline__ ull dup2(float v) { return pack2(v, v); }
__device__ __forceinline__ ull relu2(ull z) {
    float lo, hi; asm("mov.b64 {%0, %1}, %2;" : "=f"(lo), "=f"(hi) : "l"(z));
    return pack2(fmaxf(lo, 0.f), fmaxf(hi, 0.f));
}
__device__ __forceinline__ ull packmid(ull a, ull b) {
    float alo, ahi, blo, bhi;
    asm("mov.b64 {%0, %1}, %2;" : "=f"(alo), "=f"(ahi) : "l"(a));
    asm("mov.b64 {%0, %1}, %2;" : "=f"(blo), "=f"(bhi) : "l"(b));
    return pack2(ahi, blo);
}

// ---------------------------------------------------------------------------
// k0: h1_0 = relu(W1_0 @ x + b1_0).  Memory-bound (reads x, 67MB).
// ---------------------------------------------------------------------------
__global__ __launch_bounds__(256) void k0_kernel(const float* __restrict__ x,
                                                 const float* __restrict__ w1,
                                                 const float* __restrict__ b1) {
    __shared__ float4 sW1T[256];
    __shared__ float  sB1[4];
    int tid = threadIdx.x;
    if (tid < 4) sB1[tid] = b1[tid];
    sW1T[tid] = make_float4(w1[tid], w1[256 + tid], w1[512 + tid], w1[768 + tid]);
    __syncthreads();

    int n  = blockIdx.x >> 4;
    int yg = blockIdx.x & 15;
    int px = tid & 63;
    int y  = yg * 4 + (tid >> 6);

    const float* xp = x + (size_t)n * 256 * 4096 + y * 64 + px;
    float a0 = sB1[0], a1 = sB1[1], a2 = sB1[2], a3 = sB1[3];
#pragma unroll 8
    for (int c = 0; c < 256; c++) {
        float  xv = xp[c * 4096];
        float4 w  = sW1T[c];
        a0 = fmaf(xv, w.x, a0);
        a1 = fmaf(xv, w.y, a1);
        a2 = fmaf(xv, w.z, a2);
        a3 = fmaf(xv, w.w, a3);
    }
    float* hp = &g_h1[0][n][0][y][px];
    hp[0]     = fmaxf(a0, 0.f);
    hp[4096]  = fmaxf(a1, 0.f);
    hp[8192]  = fmaxf(a2, 0.f);
    hp[12288] = fmaxf(a3, 0.f);
}

// ---------------------------------------------------------------------------
// chain_kernel (block i), fp32x2-packed, 4-way channel split:
//   grid 512 = 16 img x 32 tiles (16 wide x 8 tall)
//   256 threads = 64 pixel-pairs x 4 quarters
//   conv3x3 split by INPUT channel across quarters (partials via smem),
//   fused 256-ch expand/reduce split 64 channels per quarter.
// ---------------------------------------------------------------------------
__global__ __launch_bounds__(256) void chain_kernel(
    const float* __restrict__ w1, const float* __restrict__ b1,
    const float* __restrict__ w2, const float* __restrict__ b2,
    const float* __restrict__ w3, const float* __restrict__ b3,
    int blk)
{
    __shared__ __align__(16) float s_h1[4][10][18];  // halo'd input tile (8x16 + 1px)
    __shared__ ull        s_w2d[144];        // dup-packed [j][k][dy][dx]
    __shared__ float      s_b2[4];
    __shared__ ulonglong2 s_w3d[256][2];     // dup-packed W3 rows
    __shared__ ulonglong2 s_w1d[256][2];     // dup-packed W1_{blk+1} cols
    __shared__ ull        s_b3d[256];
    __shared__ float      s_b1n[4];
    __shared__ ull        s_cp[4][4][64];    // conv partials [q][j][pair]
    __shared__ ull        s_part[3][4][64];  // fused partials [q-1][j][pair]

    int tid  = threadIdx.x;
    int pair = tid & 63;
    int q    = tid >> 6;
    int n    = blockIdx.x >> 5;
    int tile = blockIdx.x & 31;
    int ty0  = (tile >> 2) * 8;
    int tx0  = (tile & 3)  * 16;

    // weight staging (256 threads, c == tid)
    if (tid < 144) s_w2d[tid] = dup2(w2[blk * 144 + tid]);
    else if (tid < 148) s_b2[tid - 144] = b2[blk * 4 + (tid - 144)];
    if (blk < 31) {
        const float* w1n = w1 + (blk + 1) * 1024;
        int c = tid;
        float4 wr = *(const float4*)&w3[(blk * 256 + c) * 4];
        s_w3d[c][0] = make_ulonglong2(dup2(wr.x), dup2(wr.y));
        s_w3d[c][1] = make_ulonglong2(dup2(wr.z), dup2(wr.w));
        s_w1d[c][0] = make_ulonglong2(dup2(w1n[c]),       dup2(w1n[256 + c]));
        s_w1d[c][1] = make_ulonglong2(dup2(w1n[512 + c]), dup2(w1n[768 + c]));
        s_b3d[c]    = dup2(b3[blk * 256 + c]);
        if (tid >= 148 && tid < 152) s_b1n[tid - 148] = b1[(blk + 1) * 4 + (tid - 148)];
    }

    // halo tile load: 10 rows x 18 cols x 4 ch (zero pad = SAME padding)
    const float* h1base = &g_h1[blk & 1][n][0][0][0];
    for (int idx = tid; idx < 180; idx += 256) {
        int yy = idx / 18, xx = idx % 18;
        int gy = ty0 + yy - 1, gx = tx0 + xx - 1;
        bool ok = (gy >= 0 && gy < 64 && gx >= 0 && gx < 64);
#pragma unroll
        for (int k = 0; k < 4; k++)
            s_h1[k][yy][xx] = ok ? h1base[k * 4096 + gy * 64 + gx] : 0.f;
    }
    __syncthreads();

    int py = pair >> 3;          // 0..7
    int x0 = (pair & 7) * 2;     // 0,2,..,14

    // partial conv over input channel k = q (pixel pair packed)
    {
        ull p0 = (q == 0) ? dup2(s_b2[0]) : 0ull;
        ull p1 = (q == 0) ? dup2(s_b2[1]) : 0ull;
        ull p2 = (q == 0) ? dup2(s_b2[2]) : 0ull;
        ull p3 = (q == 0) ? dup2(s_b2[3]) : 0ull;
#pragma unroll
        for (int dy = 0; dy < 3; dy++) {
            const ull* rowp = (const ull*)&s_h1[q][py + dy][x0];  // 8B aligned
            ull p01 = rowp[0], p23 = rowp[1];
            ull tap0 = p01, tap1 = packmid(p01, p23), tap2 = p23;
            int wi = q * 9 + dy * 3;
            p0 = ffma2(tap0, s_w2d[wi + 0], p0);
            p1 = ffma2(tap0, s_w2d[36 + wi + 0], p1);
            p2 = ffma2(tap0, s_w2d[72 + wi + 0], p2);
            p3 = ffma2(tap0, s_w2d[108 + wi + 0], p3);
            p0 = ffma2(tap1, s_w2d[wi + 1], p0);
            p1 = ffma2(tap1, s_w2d[36 + wi + 1], p1);
            p2 = ffma2(tap1, s_w2d[72 + wi + 1], p2);
            p3 = ffma2(tap1, s_w2d[108 + wi + 1], p3);
            p0 = ffma2(tap2, s_w2d[wi + 2], p0);
            p1 = ffma2(tap2, s_w2d[36 + wi + 2], p1);
            p2 = ffma2(tap2, s_w2d[72 + wi + 2], p2);
            p3 = ffma2(tap2, s_w2d[108 + wi + 2], p3);
        }
        s_cp[q][0][pair] = p0;
        s_cp[q][1][pair] = p1;
        s_cp[q][2][pair] = p2;
        s_cp[q][3][pair] = p3;
    }
    __syncthreads();

    // every quarter-thread reduces its pair's conv partials (redundant x4, no 2nd sync)
    ull u0 = relu2(fadd2(fadd2(s_cp[0][0][pair], s_cp[1][0][pair]),
                         fadd2(s_cp[2][0][pair], s_cp[3][0][pair])));
    ull u1 = relu2(fadd2(fadd2(s_cp[0][1][pair], s_cp[1][1][pair]),
                         fadd2(s_cp[2][1][pair], s_cp[3][1][pair])));
    ull u2 = relu2(fadd2(fadd2(s_cp[0][2][pair], s_cp[1][2][pair]),
                         fadd2(s_cp[2][2][pair], s_cp[3][2][pair])));
    ull u3 = relu2(fadd2(fadd2(s_cp[0][3][pair], s_cp[1][3][pair]),
                         fadd2(s_cp[2][3][pair], s_cp[3][3][pair])));

    int gy = ty0 + py, gx = tx0 + x0;
    if (q == 0) {
        ull* h2p = (ull*)&g_h2[blk][n][0][gy][gx];   // ch stride = 2048 ull
        h2p[0] = u0; h2p[2048] = u1; h2p[4096] = u2; h2p[6144] = u3;
    }

    if (blk < 31) {
        ull a0, a1, a2, a3;
        if (q == 0) {
            a0 = dup2(s_b1n[0]); a1 = dup2(s_b1n[1]);
            a2 = dup2(s_b1n[2]); a3 = dup2(s_b1n[3]);
        } else {
            a0 = a1 = a2 = a3 = 0ull;
        }
        int c0 = q << 6;
#pragma unroll 8
        for (int cc = 0; cc < 64; cc++) {
            int c = c0 + cc;
            ulonglong2 wA = s_w3d[c][0], wB = s_w3d[c][1];
            ull z = ffma2(u0, wA.x, s_b3d[c]);
            z = ffma2(u1, wA.y, z);
            z = ffma2(u2, wB.x, z);
            z = ffma2(u3, wB.y, z);
            ull v = relu2(z);
            ulonglong2 qA = s_w1d[c][0], qB = s_w1d[c][1];
            a0 = ffma2(v, qA.x, a0);
            a1 = ffma2(v, qA.y, a1);
            a2 = ffma2(v, qB.x, a2);
            a3 = ffma2(v, qB.y, a3);
        }
        if (q > 0) {
            s_part[q - 1][0][pair] = a0;
            s_part[q - 1][1][pair] = a1;
            s_part[q - 1][2][pair] = a2;
            s_part[q - 1][3][pair] = a3;
        }
        __syncthreads();
        if (q == 0) {
            a0 = fadd2(fadd2(a0, s_part[0][0][pair]), fadd2(s_part[1][0][pair], s_part[2][0][pair]));
            a1 = fadd2(fadd2(a1, s_part[0][1][pair]), fadd2(s_part[1][1][pair], s_part[2][1][pair]));
            a2 = fadd2(fadd2(a2, s_part[0][2][pair]), fadd2(s_part[1][2][pair], s_part[2][2][pair]));
            a3 = fadd2(fadd2(a3, s_part[0][3][pair]), fadd2(s_part[1][3][pair], s_part[2][3][pair]));
            ull* hp = (ull*)&g_h1[(blk + 1) & 1][n][0][gy][gx];
            hp[0]    = relu2(a0);
            hp[2048] = relu2(a1);
            hp[4096] = relu2(a2);
            hp[6144] = relu2(a3);
        }
    }
}

// ---------------------------------------------------------------------------
// acc_kernel: out = sum_i relu(W3_i @ h2_i + b3_i), fp32x2-packed.
// Grid 1024 (16 img x 64 rows), 256 threads = 32 px-pairs x 8 ch-groups of 32.
// ---------------------------------------------------------------------------
__global__ __launch_bounds__(256) void acc_kernel(const float* __restrict__ w3,
                                                  const float* __restrict__ b3,
                                                  float* __restrict__ out) {
    __shared__ ulonglong2 s_w3d[256][2];
    __shared__ ull        s_b3d[256];
    __shared__ __align__(16) float s_u[4][64];

    int tid   = threadIdx.x;
    int n     = blockIdx.x >> 6;
    int y     = blockIdx.x & 63;
    int pair  = tid & 31;
    int grp   = tid >> 5;
    int px0   = pair * 2;
    int cbase = grp * 32;

    ull acc[32];
#pragma unroll
    for (int cc = 0; cc < 32; cc++) acc[cc] = 0ull;

    for (int i = 0; i < 32; i++) {
        __syncthreads();
        float4 wr = *(const float4*)&w3[(i * 256 + tid) * 4];
        s_w3d[tid][0] = make_ulonglong2(dup2(wr.x), dup2(wr.y));
        s_w3d[tid][1] = make_ulonglong2(dup2(wr.z), dup2(wr.w));
        s_b3d[tid]    = dup2(b3[i * 256 + tid]);
        s_u[tid >> 6][tid & 63] = g_h2[i][n][tid >> 6][y][tid & 63];
        __syncthreads();

        ull u0 = *(const ull*)&s_u[0][px0];
        ull u1 = *(const ull*)&s_u[1][px0];
        ull u2 = *(const ull*)&s_u[2][px0];
        ull u3 = *(const ull*)&s_u[3][px0];
#pragma unroll
        for (int cc = 0; cc < 32; cc++) {
            int c = cbase + cc;
            ulonglong2 wA = s_w3d[c][0], wB = s_w3d[c][1];
            ull z = ffma2(u0, wA.x, s_b3d[c]);
            z = ffma2(u1, wA.y, z);
            z = ffma2(u2, wB.x, z);
            z = ffma2(u3, wB.y, z);
            acc[cc] = fadd2(acc[cc], relu2(z));
        }
    }

#pragma unroll
    for (int cc = 0; cc < 32; cc++) {
        int c = cbase + cc;
        *(ull*)&out[(((size_t)n * 256 + c) * 64 + y) * 64 + px0] = acc[cc];
    }
}

// ---------------------------------------------------------------------------
extern "C" void kernel_launch(void* const* d_in, const int* in_sizes, int n_in,
                              void* d_out, int out_size) {
    const float* x  = (const float*)d_in[0];
    const float* w1 = (const float*)d_in[1];
    const float* b1 = (const float*)d_in[2];
    const float* w2 = (const float*)d_in[3];
    const float* b2 = (const float*)d_in[4];
    const float* w3 = (const float*)d_in[5];
    const float* b3 = (const float*)d_in[6];
    float* out = (float*)d_out;

    k0_kernel<<<256, 256>>>(x, w1, b1);
    for (int i = 0; i < 32; i++)
        chain_kernel<<<512, 256>>>(w1, b1, w2, b2, w3, b3, i);
    acc_kernel<<<1024, 256>>>(w3, b3, out);
}

// round 6
// speedup vs baseline: 1.2718x; 1.2718x over previous
#include <cuda_runtime.h>

typedef unsigned long long ull;

// Chain state: 4-channel fields only. h1 ping-pong, h2 stored per block.
__device__ float g_h1[2][16][4][64][64];   //  2.1 MB
__device__ float g_h2[32][16][4][64][64];  // 33.6 MB

// ---- packed fp32x2 helpers --------------------------------------------------
__device__ __forceinline__ ull ffma2(ull a, ull b, ull c) {
    ull d; asm("fma.rn.f32x2 %0, %1, %2, %3;" : "=l"(d) : "l"(a), "l"(b), "l"(c)); return d;
}
__device__ __forceinline__ ull fadd2(ull a, ull b) {
    ull d; asm("add.rn.f32x2 %0, %1, %2;" : "=l"(d) : "l"(a), "l"(b)); return d;
}
__device__ __forceinline__ ull pack2(float lo, float hi) {
    ull d; asm("mov.b64 %0, {%1, %2};" : "=l"(d) : "f"(lo), "f"(hi)); return d;
}
__device__ __forceinline__ ull dup2(float v) { return pack2(v, v); }
__device__ __forceinline__ ull relu2(ull z) {
    float lo, hi; asm("mov.b64 {%0, %1}, %2;" : "=f"(lo), "=f"(hi) : "l"(z));
    return pack2(fmaxf(lo, 0.f), fmaxf(hi, 0.f));
}
__device__ __forceinline__ ull packmid(ull a, ull b) {
    float alo, ahi, blo, bhi;
    asm("mov.b64 {%0, %1}, %2;" : "=f"(alo), "=f"(ahi) : "l"(a));
    asm("mov.b64 {%0, %1}, %2;" : "=f"(blo), "=f"(bhi) : "l"(b));
    return pack2(ahi, blo);
}

// ---------------------------------------------------------------------------
// k0: h1_0 = relu(W1_0 @ x + b1_0).  Memory-bound (reads x, 67MB).
// ---------------------------------------------------------------------------
__global__ __launch_bounds__(256) void k0_kernel(const float* __restrict__ x,
                                                 const float* __restrict__ w1,
                                                 const float* __restrict__ b1) {
    __shared__ float4 sW1T[256];
    __shared__ float  sB1[4];
    int tid = threadIdx.x;
    if (tid < 4) sB1[tid] = b1[tid];
    sW1T[tid] = make_float4(w1[tid], w1[256 + tid], w1[512 + tid], w1[768 + tid]);
    __syncthreads();

    int n  = blockIdx.x >> 4;
    int yg = blockIdx.x & 15;
    int px = tid & 63;
    int y  = yg * 4 + (tid >> 6);

    const float* xp = x + (size_t)n * 256 * 4096 + y * 64 + px;
    float a0 = sB1[0], a1 = sB1[1], a2 = sB1[2], a3 = sB1[3];
#pragma unroll 8
    for (int c = 0; c < 256; c++) {
        float  xv = xp[c * 4096];
        float4 w  = sW1T[c];
        a0 = fmaf(xv, w.x, a0);
        a1 = fmaf(xv, w.y, a1);
        a2 = fmaf(xv, w.z, a2);
        a3 = fmaf(xv, w.w, a3);
    }
    float* hp = &g_h1[0][n][0][y][px];
    hp[0]     = fmaxf(a0, 0.f);
    hp[4096]  = fmaxf(a1, 0.f);
    hp[8192]  = fmaxf(a2, 0.f);
    hp[12288] = fmaxf(a3, 0.f);
}

// ---------------------------------------------------------------------------
// chain_kernel (block i): 2 pixel-pairs per thread in the fused loop so one
// weight read feeds 16 FFMA2 instead of 8 (L1/shared is the measured ceiling).
//   grid 256 = 16 img x 16 tiles (16x16)
//   256 threads = 64 dual-pair slots x 4 channel-quarters
//   thread (dual,q): pairs  p0 = dual (rows 0..7),  p1 = dual+64 (rows 8..15)
//   conv3x3 split by input channel k=q across quarters (partials via smem),
//   fused 256-ch loop split 64 ch per quarter, partials via smem.
// ---------------------------------------------------------------------------
__global__ __launch_bounds__(256) void chain_kernel(
    const float* __restrict__ w1, const float* __restrict__ b1,
    const float* __restrict__ w2, const float* __restrict__ b2,
    const float* __restrict__ w3, const float* __restrict__ b3,
    int blk)
{
    __shared__ __align__(16) float s_h1[4][18][18];
    __shared__ ull        s_w2d[144];        // dup-packed [j][k][dy][dx]
    __shared__ float      s_b2[4];
    __shared__ ulonglong2 s_w3d[256][2];     // dup-packed W3 rows
    __shared__ ulonglong2 s_w1d[256][2];     // dup-packed W1_{blk+1} cols
    __shared__ ull        s_b3d[256];
    __shared__ float      s_b1n[4];
    __shared__ ull        s_cp[4][4][128];   // conv partials [q][j][pair]
    __shared__ ull        s_part[3][4][128]; // fused partials [q-1][j][pair] (reused per pair set)

    int tid  = threadIdx.x;
    int dual = tid & 63;          // 0..63
    int q    = tid >> 6;          // 0..3
    int n    = blockIdx.x >> 4;
    int tile = blockIdx.x & 15;
    int ty0  = (tile >> 2) * 16;
    int tx0  = (tile & 3)  * 16;

    int pA = dual;                // rows 0..7
    int pB = dual + 64;           // rows 8..15

    // weight staging (256 threads, c == tid)
    if (tid < 144) s_w2d[tid] = dup2(w2[blk * 144 + tid]);
    else if (tid < 148) s_b2[tid - 144] = b2[blk * 4 + (tid - 144)];
    if (blk < 31) {
        const float* w1n = w1 + (blk + 1) * 1024;
        int c = tid;
        float4 wr = *(const float4*)&w3[(blk * 256 + c) * 4];
        s_w3d[c][0] = make_ulonglong2(dup2(wr.x), dup2(wr.y));
        s_w3d[c][1] = make_ulonglong2(dup2(wr.z), dup2(wr.w));
        s_w1d[c][0] = make_ulonglong2(dup2(w1n[c]),       dup2(w1n[256 + c]));
        s_w1d[c][1] = make_ulonglong2(dup2(w1n[512 + c]), dup2(w1n[768 + c]));
        s_b3d[c]    = dup2(b3[blk * 256 + c]);
        if (tid >= 148 && tid < 152) s_b1n[tid - 148] = b1[(blk + 1) * 4 + (tid - 148)];
    }

    // halo tile load: 18x18x4 (zero pad = SAME padding)
    const float* h1base = &g_h1[blk & 1][n][0][0][0];
    for (int idx = tid; idx < 324; idx += 256) {
        int yy = idx / 18, xx = idx % 18;
        int gy = ty0 + yy - 1, gx = tx0 + xx - 1;
        bool ok = (gy >= 0 && gy < 64 && gx >= 0 && gx < 64);
#pragma unroll
        for (int k = 0; k < 4; k++)
            s_h1[k][yy][xx] = ok ? h1base[k * 4096 + gy * 64 + gx] : 0.f;
    }
    __syncthreads();

    // ---- conv3x3, input-channel k=q, for both pairs of this thread ----
#pragma unroll
    for (int s = 0; s < 2; s++) {
        int pair = s ? pB : pA;
        int py = pair >> 3;
        int x0 = (pair & 7) * 2;
        ull p0 = (q == 0) ? dup2(s_b2[0]) : 0ull;
        ull p1 = (q == 0) ? dup2(s_b2[1]) : 0ull;
        ull p2 = (q == 0) ? dup2(s_b2[2]) : 0ull;
        ull p3 = (q == 0) ? dup2(s_b2[3]) : 0ull;
#pragma unroll
        for (int dy = 0; dy < 3; dy++) {
            const ull* rowp = (const ull*)&s_h1[q][py + dy][x0];
            ull p01 = rowp[0], p23 = rowp[1];
            ull tap0 = p01, tap1 = packmid(p01, p23), tap2 = p23;
            int wi = q * 9 + dy * 3;
            p0 = ffma2(tap0, s_w2d[wi + 0], p0);
            p1 = ffma2(tap0, s_w2d[36 + wi + 0], p1);
            p2 = ffma2(tap0, s_w2d[72 + wi + 0], p2);
            p3 = ffma2(tap0, s_w2d[108 + wi + 0], p3);
            p0 = ffma2(tap1, s_w2d[wi + 1], p0);
            p1 = ffma2(tap1, s_w2d[36 + wi + 1], p1);
            p2 = ffma2(tap1, s_w2d[72 + wi + 1], p2);
            p3 = ffma2(tap1, s_w2d[108 + wi + 1], p3);
            p0 = ffma2(tap2, s_w2d[wi + 2], p0);
            p1 = ffma2(tap2, s_w2d[36 + wi + 2], p1);
            p2 = ffma2(tap2, s_w2d[72 + wi + 2], p2);
            p3 = ffma2(tap2, s_w2d[108 + wi + 2], p3);
        }
        s_cp[q][0][pair] = p0;
        s_cp[q][1][pair] = p1;
        s_cp[q][2][pair] = p2;
        s_cp[q][3][pair] = p3;
    }
    __syncthreads();

    // every quarter reduces its own pairs' conv partials (redundant x4, no extra sync)
    ull uA0 = relu2(fadd2(fadd2(s_cp[0][0][pA], s_cp[1][0][pA]), fadd2(s_cp[2][0][pA], s_cp[3][0][pA])));
    ull uA1 = relu2(fadd2(fadd2(s_cp[0][1][pA], s_cp[1][1][pA]), fadd2(s_cp[2][1][pA], s_cp[3][1][pA])));
    ull uA2 = relu2(fadd2(fadd2(s_cp[0][2][pA], s_cp[1][2][pA]), fadd2(s_cp[2][2][pA], s_cp[3][2][pA])));
    ull uA3 = relu2(fadd2(fadd2(s_cp[0][3][pA], s_cp[1][3][pA]), fadd2(s_cp[2][3][pA], s_cp[3][3][pA])));
    ull uB0 = relu2(fadd2(fadd2(s_cp[0][0][pB], s_cp[1][0][pB]), fadd2(s_cp[2][0][pB], s_cp[3][0][pB])));
    ull uB1 = relu2(fadd2(fadd2(s_cp[0][1][pB], s_cp[1][1][pB]), fadd2(s_cp[2][1][pB], s_cp[3][1][pB])));
    ull uB2 = relu2(fadd2(fadd2(s_cp[0][2][pB], s_cp[1][2][pB]), fadd2(s_cp[2][2][pB], s_cp[3][2][pB])));
    ull uB3 = relu2(fadd2(fadd2(s_cp[0][3][pB], s_cp[1][3][pB]), fadd2(s_cp[2][3][pB], s_cp[3][3][pB])));

    int gyA = ty0 + (pA >> 3), gxA = tx0 + (pA & 7) * 2;
    int gyB = ty0 + (pB >> 3), gxB = tx0 + (pB & 7) * 2;
    if (q == 0) {
        ull* hA = (ull*)&g_h2[blk][n][0][gyA][gxA];   // ch stride = 2048 ull
        hA[0] = uA0; hA[2048] = uA1; hA[4096] = uA2; hA[6144] = uA3;
        ull* hB = (ull*)&g_h2[blk][n][0][gyB][gxB];
        hB[0] = uB0; hB[2048] = uB1; hB[4096] = uB2; hB[6144] = uB3;
    }

    if (blk < 31) {
        ull aA0, aA1, aA2, aA3, aB0, aB1, aB2, aB3;
        if (q == 0) {
            aA0 = dup2(s_b1n[0]); aA1 = dup2(s_b1n[1]); aA2 = dup2(s_b1n[2]); aA3 = dup2(s_b1n[3]);
            aB0 = aA0; aB1 = aA1; aB2 = aA2; aB3 = aA3;
        } else {
            aA0 = aA1 = aA2 = aA3 = 0ull;
            aB0 = aB1 = aB2 = aB3 = 0ull;
        }
        int c0 = q << 6;
#pragma unroll 4
        for (int cc = 0; cc < 64; cc++) {
            int c = c0 + cc;
            ulonglong2 wA = s_w3d[c][0], wB = s_w3d[c][1];
            ull bb = s_b3d[c];
            ulonglong2 qA = s_w1d[c][0], qB = s_w1d[c][1];
            // pair A
            ull zA = ffma2(uA0, wA.x, bb);
            zA = ffma2(uA1, wA.y, zA);
            zA = ffma2(uA2, wB.x, zA);
            zA = ffma2(uA3, wB.y, zA);
            ull vA = relu2(zA);
            aA0 = ffma2(vA, qA.x, aA0);
            aA1 = ffma2(vA, qA.y, aA1);
            aA2 = ffma2(vA, qB.x, aA2);
            aA3 = ffma2(vA, qB.y, aA3);
            // pair B (independent chain — ILP)
            ull zB = ffma2(uB0, wA.x, bb);
            zB = ffma2(uB1, wA.y, zB);
            zB = ffma2(uB2, wB.x, zB);
            zB = ffma2(uB3, wB.y, zB);
            ull vB = relu2(zB);
            aB0 = ffma2(vB, qA.x, aB0);
            aB1 = ffma2(vB, qA.y, aB1);
            aB2 = ffma2(vB, qB.x, aB2);
            aB3 = ffma2(vB, qB.y, aB3);
        }
        // combine quarters: pair A then pair B through the same smem buffer
        if (q > 0) {
            s_part[q - 1][0][pA] = aA0; s_part[q - 1][1][pA] = aA1;
            s_part[q - 1][2][pA] = aA2; s_part[q - 1][3][pA] = aA3;
            s_part[q - 1][0][pB] = aB0; s_part[q - 1][1][pB] = aB1;
            s_part[q - 1][2][pB] = aB2; s_part[q - 1][3][pB] = aB3;
        }
        __syncthreads();
        if (q == 0) {
            aA0 = fadd2(fadd2(aA0, s_part[0][0][pA]), fadd2(s_part[1][0][pA], s_part[2][0][pA]));
            aA1 = fadd2(fadd2(aA1, s_part[0][1][pA]), fadd2(s_part[1][1][pA], s_part[2][1][pA]));
            aA2 = fadd2(fadd2(aA2, s_part[0][2][pA]), fadd2(s_part[1][2][pA], s_part[2][2][pA]));
            aA3 = fadd2(fadd2(aA3, s_part[0][3][pA]), fadd2(s_part[1][3][pA], s_part[2][3][pA]));
            ull* hp = (ull*)&g_h1[(blk + 1) & 1][n][0][gyA][gxA];
            hp[0]    = relu2(aA0);
            hp[2048] = relu2(aA1);
            hp[4096] = relu2(aA2);
            hp[6144] = relu2(aA3);
            aB0 = fadd2(fadd2(aB0, s_part[0][0][pB]), fadd2(s_part[1][0][pB], s_part[2][0][pB]));
            aB1 = fadd2(fadd2(aB1, s_part[0][1][pB]), fadd2(s_part[1][1][pB], s_part[2][1][pB]));
            aB2 = fadd2(fadd2(aB2, s_part[0][2][pB]), fadd2(s_part[1][2][pB], s_part[2][2][pB]));
            aB3 = fadd2(fadd2(aB3, s_part[0][3][pB]), fadd2(s_part[1][3][pB], s_part[2][3][pB]));
            ull* hq = (ull*)&g_h1[(blk + 1) & 1][n][0][gyB][gxB];
            hq[0]    = relu2(aB0);
            hq[2048] = relu2(aB1);
            hq[4096] = relu2(aB2);
            hq[6144] = relu2(aB3);
        }
    }
}

// ---------------------------------------------------------------------------
// acc_kernel: out = sum_i relu(W3_i @ h2_i + b3_i).
// 2 pixel-pairs per thread: grid 1024 (16 img x 64 rows),
// 256 threads = 16 dual-pair slots x 16 ch-groups of 16 channels.
// 32 packed accumulators (16 ch x 2 pairs) per thread.
// ---------------------------------------------------------------------------
__global__ __launch_bounds__(256) void acc_kernel(const float* __restrict__ w3,
                                                  const float* __restrict__ b3,
                                                  float* __restrict__ out) {
    __shared__ ulonglong2 s_w3d[256][2];
    __shared__ ull        s_b3d[256];
    __shared__ __align__(16) float s_u[4][64];

    int tid   = threadIdx.x;
    int n     = blockIdx.x >> 6;
    int y     = blockIdx.x & 63;
    int dual  = tid & 15;          // 0..15 -> pairs dual and dual+16
    int grp   = tid >> 4;          // 0..15 -> channels [grp*16, grp*16+16)
    int pxA   = dual * 2;          // pixels 0..31
    int pxB   = pxA + 32;          // pixels 32..63
    int cbase = grp * 16;

    ull accA[16], accB[16];
#pragma unroll
    for (int cc = 0; cc < 16; cc++) { accA[cc] = 0ull; accB[cc] = 0ull; }

    for (int i = 0; i < 32; i++) {
        __syncthreads();
        float4 wr = *(const float4*)&w3[(i * 256 + tid) * 4];
        s_w3d[tid][0] = make_ulonglong2(dup2(wr.x), dup2(wr.y));
        s_w3d[tid][1] = make_ulonglong2(dup2(wr.z), dup2(wr.w));
        s_b3d[tid]    = dup2(b3[i * 256 + tid]);
        s_u[tid >> 6][tid & 63] = g_h2[i][n][tid >> 6][y][tid & 63];
        __syncthreads();

        ull uA0 = *(const ull*)&s_u[0][pxA];
        ull uA1 = *(const ull*)&s_u[1][pxA];
        ull uA2 = *(const ull*)&s_u[2][pxA];
        ull uA3 = *(const ull*)&s_u[3][pxA];
        ull uB0 = *(const ull*)&s_u[0][pxB];
        ull uB1 = *(const ull*)&s_u[1][pxB];
        ull uB2 = *(const ull*)&s_u[2][pxB];
        ull uB3 = *(const ull*)&s_u[3][pxB];
#pragma unroll
        for (int cc = 0; cc < 16; cc++) {
            int c = cbase + cc;
            ulonglong2 wA = s_w3d[c][0], wB = s_w3d[c][1];
            ull bb = s_b3d[c];
            ull zA = ffma2(uA0, wA.x, bb);
            zA = ffma2(uA1, wA.y, zA);
            zA = ffma2(uA2, wB.x, zA);
            zA = ffma2(uA3, wB.y, zA);
            accA[cc] = fadd2(accA[cc], relu2(zA));
            ull zB = ffma2(uB0, wA.x, bb);
            zB = ffma2(uB1, wA.y, zB);
            zB = ffma2(uB2, wB.x, zB);
            zB = ffma2(uB3, wB.y, zB);
            accB[cc] = fadd2(accB[cc], relu2(zB));
        }
    }

#pragma unroll
    for (int cc = 0; cc < 16; cc++) {
        int c = cbase + cc;
        size_t base = (((size_t)n * 256 + c) * 64 + y) * 64;
        *(ull*)&out[base + pxA] = accA[cc];
        *(ull*)&out[base + pxB] = accB[cc];
    }
}

// ---------------------------------------------------------------------------
extern "C" void kernel_launch(void* const* d_in, const int* in_sizes, int n_in,
                              void* d_out, int out_size) {
    const float* x  = (const float*)d_in[0];
    const float* w1 = (const float*)d_in[1];
    const float* b1 = (const float*)d_in[2];
    const float* w2 = (const float*)d_in[3];
    const float* b2 = (const float*)d_in[4];
    const float* w3 = (const float*)d_in[5];
    const float* b3 = (const float*)d_in[6];
    float* out = (float*)d_out;

    k0_kernel<<<256, 256>>>(x, w1, b1);
    for (int i = 0; i < 32; i++)
        chain_kernel<<<256, 256>>>(w1, b1, w2, b2, w3, b3, i);
    acc_kernel<<<1024, 256>>>(w3, b3, out);
}